// round 9
// baseline (speedup 1.0000x reference)
#include <cuda_runtime.h>
#include <math.h>

// ---------------- problem constants ----------------
#define H1 128
#define W1 160
#define H2 256
#define W2 320
#define HWS1 (H1*W1)   // 20480
#define HWS2 (H2*W2)   // 81920
#define ND1 48
#define ND2 8
#define C1 32
#define C2 16

// ---------------- scratch (device globals; no allocation allowed) ----------------
__device__ float g_rot[2][2][9];
__device__ float g_trans[2][2][3];
__device__ float g_dmin, g_dstep;
__device__ float g_pad[32];

// 27 channel-reduced conv planes. stage1: 27*48*20480 floats (106MB). stage2 fits.
__device__ float g_G[27 * ND1 * HWS1];
__device__ float g_cost[ND1 * HWS1];       // stage2: 8*81920 fits
__device__ float g_bs[2 * HWS2];           // stage-2 per-pixel depth base/step
// channel-interleaved features: (3, C/4, HW) of float4
__device__ float4 g_ft[3 * (C2/4) * HWS2];

// ---------------- setup ----------------
__device__ void mat4_inv_d(const double* M, double* out) {
    double a[4][8];
    for (int i = 0; i < 4; i++)
        for (int j = 0; j < 4; j++) { a[i][j] = M[i*4+j]; a[i][j+4] = (i==j) ? 1.0 : 0.0; }
    for (int col = 0; col < 4; col++) {
        int piv = col; double best = fabs(a[col][col]);
        for (int r = col+1; r < 4; r++) if (fabs(a[r][col]) > best) { best = fabs(a[r][col]); piv = r; }
        if (piv != col) for (int j = 0; j < 8; j++) { double t = a[col][j]; a[col][j] = a[piv][j]; a[piv][j] = t; }
        double d = a[col][col];
        for (int j = 0; j < 8; j++) a[col][j] /= d;
        for (int r = 0; r < 4; r++) if (r != col) {
            double f = a[r][col];
            for (int j = 0; j < 8; j++) a[r][j] -= f * a[col][j];
        }
    }
    for (int i = 0; i < 4; i++) for (int j = 0; j < 4; j++) out[i*4+j] = a[i][j+4];
}

__global__ void setup_kernel(const float* __restrict__ proj1,
                             const float* __restrict__ proj2,
                             const float* __restrict__ depthv) {
    if (threadIdx.x != 0 || blockIdx.x != 0) return;
    for (int s = 0; s < 2; s++) {
        const float* P = s ? proj2 : proj1;   // (3 views, 2, 4, 4)
        double comp[3][16];
        for (int v = 0; v < 3; v++) {
            const float* E   = P + v*32;
            const float* Kin = P + v*32 + 16;
            for (int i = 0; i < 16; i++) comp[v][i] = (double)E[i];
            for (int i = 0; i < 3; i++)
                for (int j = 0; j < 4; j++) {
                    double t = 0.0;
                    for (int k = 0; k < 3; k++) t += (double)Kin[i*4+k] * (double)E[k*4+j];
                    comp[v][i*4+j] = t;
                }
        }
        double inv[16];
        mat4_inv_d(comp[0], inv);
        for (int v = 1; v < 3; v++) {
            double R[16];
            for (int i = 0; i < 4; i++)
                for (int j = 0; j < 4; j++) {
                    double t = 0.0;
                    for (int k = 0; k < 4; k++) t += comp[v][i*4+k] * inv[k*4+j];
                    R[i*4+j] = t;
                }
            for (int i = 0; i < 3; i++) {
                for (int j = 0; j < 3; j++) g_rot[s][v-1][i*3+j] = (float)R[i*4+j];
                g_trans[s][v-1][i] = (float)R[i*4+3];
            }
        }
    }
    g_dmin  = depthv[0];
    g_dstep = (depthv[ND1-1] - depthv[0]) / (float)(ND1 - 1);
}

__global__ void pad_kernel(int v) {
    if (blockIdx.x == 0 && threadIdx.x == 0) g_pad[v] = (float)v;
}

// ---------------- feature transpose: (3,C,H,W) -> (3,C/4,HW) of float4 ----------------
template<int C, int HW>
__global__ void __launch_bounds__(256)
transpose_kernel(const float* __restrict__ feats) {
    int i = blockIdx.x * blockDim.x + threadIdx.x;
    if (i >= 3 * (C/4) * HW) return;
    int hw = i % HW;
    int t  = i / HW;
    int cg = t % (C/4);
    int v  = t / (C/4);
    const float* src = feats + ((size_t)(v*C + cg*4)) * HW + hw;
    float4 val;
    val.x = src[0];
    val.y = src[HW];
    val.z = src[2*(size_t)HW];
    val.w = src[3*(size_t)HW];
    g_ft[i] = val;
}

// ---------------- 2x bilinear upsample sample ----------------
__device__ __forceinline__ float resize2x_sample(const float* __restrict__ src, int h, int w) {
    float fy = 0.5f * (float)h - 0.25f;
    float fx = 0.5f * (float)w - 0.25f;
    float y0f = floorf(fy), x0f = floorf(fx);
    float ty = fy - y0f, tx = fx - x0f;
    int y0 = (int)y0f, x0 = (int)x0f;
    int y0c = min(max(y0, 0), H1-1), y1c = min(max(y0+1, 0), H1-1);
    int x0c = min(max(x0, 0), W1-1), x1c = min(max(x0+1, 0), W1-1);
    float v00 = src[y0c*W1 + x0c], v01 = src[y0c*W1 + x1c];
    float v10 = src[y1c*W1 + x0c], v11 = src[y1c*W1 + x1c];
    return (v00*(1.f-tx) + v01*tx)*(1.f-ty) + (v10*(1.f-tx) + v11*tx)*ty;
}

__global__ void bs2_kernel(const float* __restrict__ d1, const float* __restrict__ v1) {
    int p = blockIdx.x * blockDim.x + threadIdx.x;
    if (p >= HWS2) return;
    int h = p / W2, w = p % W2;
    float cd = resize2x_sample(d1, h, w);
    float cv = resize2x_sample(v1, h, w);
    float low  = -fminf(cd, cv);
    g_bs[p]        = cd + low + 1e-12f;
    g_bs[HWS2 + p] = (cv - low) / (float)(ND2 - 1);
}

// ---------------- projection helper ----------------
template<int H, int W>
__device__ __forceinline__ void project_offsets(
    const float* __restrict__ R, const float* __restrict__ T,
    float fx, float fy, float depth, int* off, float* wt) {
    float px = (R[0]*fx + R[1]*fy + R[2]) * depth + T[0];
    float py = (R[3]*fx + R[4]*fy + R[5]) * depth + T[1];
    float pz = (R[6]*fx + R[7]*fy + R[8]) * depth + T[2];
    float iz = __fdividef(1.0f, pz);
    float gx = px * iz / (0.5f*(float)(W-1)) - 1.0f;
    float gy = py * iz / (0.5f*(float)(H-1)) - 1.0f;
    float ix = ((gx + 1.0f)*(float)W - 1.0f) * 0.5f;
    float iy = ((gy + 1.0f)*(float)H - 1.0f) * 0.5f;
    ix = fminf(fmaxf(ix, -8.0f), (float)(W+8));
    iy = fminf(fmaxf(iy, -8.0f), (float)(H+8));
    float x0f = floorf(ix), y0f = floorf(iy);
    float tx = ix - x0f, ty = iy - y0f;
    int x0 = (int)x0f, y0 = (int)y0f;
    bool vx0 = (x0   >= 0) && (x0   <= W-1);
    bool vx1 = (x0+1 >= 0) && (x0+1 <= W-1);
    bool vy0 = (y0   >= 0) && (y0   <= H-1);
    bool vy1 = (y0+1 >= 0) && (y0+1 <= H-1);
    int x0c = min(max(x0,   0), W-1), x1c = min(max(x0+1, 0), W-1);
    int y0c = min(max(y0,   0), H-1), y1c = min(max(y0+1, 0), H-1);
    off[0] = y0c*W + x0c;  off[1] = y0c*W + x1c;
    off[2] = y1c*W + x0c;  off[3] = y1c*W + x1c;
    wt[0] = (vx0 && vy0) ? (1.f-tx)*(1.f-ty) : 0.f;
    wt[1] = (vx1 && vy0) ? tx*(1.f-ty)       : 0.f;
    wt[2] = (vx0 && vy1) ? (1.f-tx)*ty       : 0.f;
    wt[3] = (vx1 && vy1) ? tx*ty             : 0.f;
}

__device__ __forceinline__ float4 gather4(const float4* __restrict__ b,
                                          const int* off, const float* wt) {
    float4 p0 = b[off[0]], p1 = b[off[1]], p2 = b[off[2]], p3 = b[off[3]];
    float4 a;
    a.x = wt[0]*p0.x + wt[1]*p1.x + wt[2]*p2.x + wt[3]*p3.x;
    a.y = wt[0]*p0.y + wt[1]*p1.y + wt[2]*p2.y + wt[3]*p3.y;
    a.z = wt[0]*p0.z + wt[1]*p1.z + wt[2]*p2.z + wt[3]*p3.z;
    a.w = wt[0]*p0.w + wt[1]*p1.w + wt[2]*p2.w + wt[3]*p3.w;
    return a;
}

__device__ __forceinline__ float4 var3(float4 r, float4 a1, float4 a2) {
    float4 o;
    float s, q, m;
    s = r.x + a1.x + a2.x; q = r.x*r.x + a1.x*a1.x + a2.x*a2.x;
    m = s*(1.f/3.f); o.x = q*(1.f/3.f) - m*m;
    s = r.y + a1.y + a2.y; q = r.y*r.y + a1.y*a1.y + a2.y*a2.y;
    m = s*(1.f/3.f); o.y = q*(1.f/3.f) - m*m;
    s = r.z + a1.z + a2.z; q = r.z*r.z + a1.z*a1.z + a2.z*a2.z;
    m = s*(1.f/3.f); o.z = q*(1.f/3.f) - m*m;
    s = r.w + a1.w + a2.w; q = r.w*r.w + a1.w*a1.w + a2.w*a2.w;
    m = s*(1.f/3.f); o.w = q*(1.f/3.f) - m*m;
    return o;
}

// ---------------- pass1: depth-pair per thread, phase-split ----------------
// Phase A: compute var4[CG] for both depths (all gathers, few accumulators).
// Phase B: for each of the 27 taps, dot var against the tap's weight vector
// and store immediately -> only 2 live accumulators instead of 54.
template<int C, int D, int H, int W, bool STAGE2>
__global__ void __launch_bounds__(128, 3)
pass1_kernel(const float* __restrict__ wconv,   // (C, 27)
             int stage) {
    constexpr int HW = H * W;
    constexpr int CG = C / 4;

    // transposed weights: sw[k*C + c] = wconv[c*27 + k], read as float4 over c
    __shared__ float sw[27 * C];
    for (int i = threadIdx.x; i < 27*C; i += blockDim.x) {
        int k = i / C, c = i % C;
        sw[i] = wconv[c*27 + k];
    }
    __syncthreads();
    const float4* swv = reinterpret_cast<const float4*>(sw);

    int idx = blockIdx.x * blockDim.x + threadIdx.x;
    if (idx >= (D/2) * HW) return;
    int hw = idx % HW;
    int dp = idx / HW;
    int d0 = 2*dp;
    int h = hw / W, w = hw % W;

    float base, step;
    if (STAGE2) { base = g_bs[hw]; step = g_bs[HWS2 + hw]; }
    else        { base = g_dmin;   step = g_dstep; }
    float dep0 = fmaf(step, (float)d0,     base);
    float dep1 = fmaf(step, (float)(d0+1), base);

    int   off[2][2][4];   // [depth][view][corner]
    float wt[2][2][4];
    float fx = (float)w, fy = (float)h;
    #pragma unroll
    for (int v = 0; v < 2; v++) {
        const float* R = g_rot[stage][v];
        const float* T = g_trans[stage][v];
        project_offsets<H, W>(R, T, fx, fy, dep0, off[0][v], wt[0][v]);
        project_offsets<H, W>(R, T, fx, fy, dep1, off[1][v], wt[1][v]);
    }

    const float4* ft0 = g_ft + hw;
    const float4* ft1 = g_ft + (size_t)(1*CG) * HW;
    const float4* ft2 = g_ft + (size_t)(2*CG) * HW;

    // ---- phase A: per-channel-group variance for both depths ----
    float4 var0[CG], var1[CG];
    #pragma unroll
    for (int cg = 0; cg < CG; cg++) {
        float4 r4 = ft0[(size_t)cg * HW];               // shared across pair
        const float4* b1 = ft1 + (size_t)cg * HW;
        const float4* b2 = ft2 + (size_t)cg * HW;
        var0[cg] = var3(r4, gather4(b1, off[0][0], wt[0][0]),
                            gather4(b2, off[0][1], wt[0][1]));
        var1[cg] = var3(r4, gather4(b1, off[1][0], wt[1][0]),
                            gather4(b2, off[1][1], wt[1][1]));
    }

    // ---- phase B: 27 tap-dots, store immediately ----
    float* out0 = g_G + (size_t)d0*HW + hw;
    float* out1 = out0 + HW;
    #pragma unroll
    for (int k = 0; k < 27; k++) {
        float s0 = 0.f, s1 = 0.f;
        #pragma unroll
        for (int cg = 0; cg < CG; cg++) {
            float4 wv = swv[k*CG + cg];
            s0 = fmaf(var0[cg].x, wv.x, s0);
            s0 = fmaf(var0[cg].y, wv.y, s0);
            s0 = fmaf(var0[cg].z, wv.z, s0);
            s0 = fmaf(var0[cg].w, wv.w, s0);
            s1 = fmaf(var1[cg].x, wv.x, s1);
            s1 = fmaf(var1[cg].y, wv.y, s1);
            s1 = fmaf(var1[cg].z, wv.z, s1);
            s1 = fmaf(var1[cg].w, wv.w, s1);
        }
        out0[(size_t)k*(D*HW)] = s0;
        out1[(size_t)k*(D*HW)] = s1;
    }
}

// ---------------- cost: 27-tap shifted-plane sum, 4 pixels per thread ----------------
template<int D, int H, int W>
__global__ void __launch_bounds__(256)
cost_kernel(const float* __restrict__ bias) {
    constexpr int HW = H * W;
    constexpr int W4 = W / 4;
    int t = blockIdx.x * blockDim.x + threadIdx.x;
    if (t >= D * H * W4) return;
    int wq = (t % W4) * 4;
    int r  = t / W4;
    int h = r % H;
    int d = r / H;

    float bb = bias[0];
    float4 s = make_float4(bb, bb, bb, bb);

    #pragma unroll
    for (int kd = 0; kd < 3; kd++) {
        int dd = d + kd - 1;
        if (dd < 0 || dd >= D) continue;
        #pragma unroll
        for (int kh = 0; kh < 3; kh++) {
            int hh = h + kh - 1;
            if (hh < 0 || hh >= H) continue;
            #pragma unroll
            for (int kw = 0; kw < 3; kw++) {
                const float* row = g_G + (size_t)(kd*9 + kh*3 + kw)*(D*HW)
                                       + (size_t)dd*HW + (size_t)hh*W;
                float4 v = *reinterpret_cast<const float4*>(row + wq);
                if (kw == 0) {          // shift -1
                    float left = (wq > 0) ? row[wq-1] : 0.f;
                    s.x += left; s.y += v.x; s.z += v.y; s.w += v.z;
                } else if (kw == 1) {   // shift 0
                    s.x += v.x; s.y += v.y; s.z += v.z; s.w += v.w;
                } else {                // shift +1
                    float right = (wq + 4 < W) ? row[wq+4] : 0.f;
                    s.x += v.y; s.y += v.z; s.z += v.w; s.w += right;
                }
            }
        }
    }
    *reinterpret_cast<float4*>(g_cost + (size_t)d*HW + (size_t)h*W + wq) = s;
}

// ---------------- per-pixel epilogue ----------------
template<int D, int H, int W, bool STAGE2>
__global__ void __launch_bounds__(256)
pixel_kernel(float* __restrict__ outd,
             float* __restrict__ outc,
             float* __restrict__ outv) {
    constexpr int HW = H * W;
    int p = blockIdx.x * blockDim.x + threadIdx.x;
    if (p >= HW) return;

    float e[D];
    float mx = -1e30f;
    #pragma unroll
    for (int d = 0; d < D; d++) { e[d] = g_cost[(size_t)d*HW + p]; mx = fmaxf(mx, e[d]); }
    float sum = 0.f;
    #pragma unroll
    for (int d = 0; d < D; d++) { e[d] = expf(e[d] - mx); sum += e[d]; }
    float inv = 1.0f / sum;
    float m1 = 0.f;
    #pragma unroll
    for (int d = 0; d < D; d++) {
        float pr = e[d] * inv;
        e[d] = pr;
        m1 += pr * (float)d;
    }

    float base, step;
    if (STAGE2) { base = g_bs[p]; step = g_bs[HWS2 + p]; }
    else        { base = g_dmin; step = g_dstep; }

    float depth = fmaf(step, m1, base);
    float var = 0.f;
    #pragma unroll
    for (int d = 0; d < D; d++) {
        float t = step * ((float)d - m1);
        var += e[d] * t * t;
    }
    int di = min(max((int)m1, 0), D-1);
    float conf = 0.f;
    #pragma unroll
    for (int d = 0; d < D; d++)
        if (d >= di-1 && d <= di+2) conf += e[d];

    outd[p] = depth;
    outc[p] = conf;
    outv[p] = 1.5f * sqrtf(fmaxf(var, 0.f));
}

// ---------------- launch ----------------
extern "C" void kernel_launch(void* const* d_in, const int* in_sizes, int n_in,
                              void* d_out, int out_size) {
    const float* feats1 = (const float*)d_in[0];
    const float* feats2 = (const float*)d_in[1];
    const float* proj1  = (const float*)d_in[2];
    const float* proj2  = (const float*)d_in[3];
    const float* depthv = (const float*)d_in[4];
    const float* w1     = (const float*)d_in[6];
    const float* b1     = (const float*)d_in[7];
    const float* w2     = (const float*)d_in[8];
    const float* b2     = (const float*)d_in[9];

    float* out = (float*)d_out;
    float* o_d1 = out;
    float* o_c1 = out + HWS1;
    float* o_v1 = out + 2*HWS1;
    float* o_d2 = out + 3*HWS1;
    float* o_c2 = out + 3*HWS1 + HWS2;
    float* o_v2 = out + 3*HWS1 + 2*HWS2;

    setup_kernel<<<1, 1>>>(proj1, proj2, depthv);                             // 1
    transpose_kernel<C1, HWS1><<<(3*(C1/4)*HWS1 + 255)/256, 256>>>(feats1);   // 2
    pad_kernel<<<1, 32>>>(0);                                                  // 3

    // ---- stage 1 (C=32, D=48, 128x160) ----
    {
        int nthr = (ND1/2) * HWS1;   // 491520
        pass1_kernel<C1, ND1, H1, W1, false>                                   // 4 (profiled)
            <<<(nthr + 127)/128, 128>>>(w1, 0);
        cost_kernel<ND1, H1, W1>
            <<<(ND1*H1*(W1/4) + 255)/256, 256>>>(b1);
        pixel_kernel<ND1, H1, W1, false>
            <<<(HWS1 + 255)/256, 256>>>(o_d1, o_c1, o_v1);
    }

    // ---- stage 2 (C=16, D=8, 256x320) ----
    {
        int nthr = (ND2/2) * HWS2;   // 327680
        transpose_kernel<C2, HWS2><<<(3*(C2/4)*HWS2 + 255)/256, 256>>>(feats2);
        bs2_kernel<<<(HWS2 + 255)/256, 256>>>(o_d1, o_v1);
        pass1_kernel<C2, ND2, H2, W2, true>
            <<<(nthr + 127)/128, 128>>>(w2, 1);
        cost_kernel<ND2, H2, W2>
            <<<(ND2*H2*(W2/4) + 255)/256, 256>>>(b2);
        pixel_kernel<ND2, H2, W2, true>
            <<<(HWS2 + 255)/256, 256>>>(o_d2, o_c2, o_v2);
    }
}

// round 12
// speedup vs baseline: 1.0111x; 1.0111x over previous
#include <cuda_runtime.h>
#include <math.h>

// ---------------- problem constants ----------------
#define H1 128
#define W1 160
#define H2 256
#define W2 320
#define HWS1 (H1*W1)   // 20480
#define HWS2 (H2*W2)   // 81920
#define ND1 48
#define ND2 8
#define C1 32
#define C2 16

// ---------------- scratch (device globals; no allocation allowed) ----------------
__device__ float g_rot[2][2][9];
__device__ float g_trans[2][2][3];
__device__ float g_dmin, g_dstep;
__device__ float g_pad[32];

// 27 channel-reduced conv planes. stage1: 27*48*20480 floats (106MB). stage2 fits.
__device__ float g_G[27 * ND1 * HWS1];
__device__ float g_cost[ND1 * HWS1];       // stage2: 8*81920 fits
__device__ float g_bs[2 * HWS2];           // stage-2 per-pixel depth base/step
// channel-interleaved features: (3, C/4, HW) of float4
__device__ float4 g_ft[3 * (C2/4) * HWS2];

// ---------------- setup ----------------
__device__ void mat4_inv_d(const double* M, double* out) {
    double a[4][8];
    for (int i = 0; i < 4; i++)
        for (int j = 0; j < 4; j++) { a[i][j] = M[i*4+j]; a[i][j+4] = (i==j) ? 1.0 : 0.0; }
    for (int col = 0; col < 4; col++) {
        int piv = col; double best = fabs(a[col][col]);
        for (int r = col+1; r < 4; r++) if (fabs(a[r][col]) > best) { best = fabs(a[r][col]); piv = r; }
        if (piv != col) for (int j = 0; j < 8; j++) { double t = a[col][j]; a[col][j] = a[piv][j]; a[piv][j] = t; }
        double d = a[col][col];
        for (int j = 0; j < 8; j++) a[col][j] /= d;
        for (int r = 0; r < 4; r++) if (r != col) {
            double f = a[r][col];
            for (int j = 0; j < 8; j++) a[r][j] -= f * a[col][j];
        }
    }
    for (int i = 0; i < 4; i++) for (int j = 0; j < 4; j++) out[i*4+j] = a[i][j+4];
}

__global__ void setup_kernel(const float* __restrict__ proj1,
                             const float* __restrict__ proj2,
                             const float* __restrict__ depthv) {
    if (threadIdx.x != 0 || blockIdx.x != 0) return;
    for (int s = 0; s < 2; s++) {
        const float* P = s ? proj2 : proj1;   // (3 views, 2, 4, 4)
        double comp[3][16];
        for (int v = 0; v < 3; v++) {
            const float* E   = P + v*32;
            const float* Kin = P + v*32 + 16;
            for (int i = 0; i < 16; i++) comp[v][i] = (double)E[i];
            for (int i = 0; i < 3; i++)
                for (int j = 0; j < 4; j++) {
                    double t = 0.0;
                    for (int k = 0; k < 3; k++) t += (double)Kin[i*4+k] * (double)E[k*4+j];
                    comp[v][i*4+j] = t;
                }
        }
        double inv[16];
        mat4_inv_d(comp[0], inv);
        for (int v = 1; v < 3; v++) {
            double R[16];
            for (int i = 0; i < 4; i++)
                for (int j = 0; j < 4; j++) {
                    double t = 0.0;
                    for (int k = 0; k < 4; k++) t += comp[v][i*4+k] * inv[k*4+j];
                    R[i*4+j] = t;
                }
            for (int i = 0; i < 3; i++) {
                for (int j = 0; j < 3; j++) g_rot[s][v-1][i*3+j] = (float)R[i*4+j];
                g_trans[s][v-1][i] = (float)R[i*4+3];
            }
        }
    }
    g_dmin  = depthv[0];
    g_dstep = (depthv[ND1-1] - depthv[0]) / (float)(ND1 - 1);
}

__global__ void pad_kernel(int v) {
    if (blockIdx.x == 0 && threadIdx.x == 0) g_pad[v] = (float)v;
}

// ---------------- feature transpose: (3,C,H,W) -> (3,C/4,HW) of float4 ----------------
template<int C, int HW>
__global__ void __launch_bounds__(256)
transpose_kernel(const float* __restrict__ feats) {
    int i = blockIdx.x * blockDim.x + threadIdx.x;
    if (i >= 3 * (C/4) * HW) return;
    int hw = i % HW;
    int t  = i / HW;
    int cg = t % (C/4);
    int v  = t / (C/4);
    const float* src = feats + ((size_t)(v*C + cg*4)) * HW + hw;
    float4 val;
    val.x = src[0];
    val.y = src[HW];
    val.z = src[2*(size_t)HW];
    val.w = src[3*(size_t)HW];
    g_ft[i] = val;
}

// ---------------- 2x bilinear upsample sample ----------------
__device__ __forceinline__ float resize2x_sample(const float* __restrict__ src, int h, int w) {
    float fy = 0.5f * (float)h - 0.25f;
    float fx = 0.5f * (float)w - 0.25f;
    float y0f = floorf(fy), x0f = floorf(fx);
    float ty = fy - y0f, tx = fx - x0f;
    int y0 = (int)y0f, x0 = (int)x0f;
    int y0c = min(max(y0, 0), H1-1), y1c = min(max(y0+1, 0), H1-1);
    int x0c = min(max(x0, 0), W1-1), x1c = min(max(x0+1, 0), W1-1);
    float v00 = src[y0c*W1 + x0c], v01 = src[y0c*W1 + x1c];
    float v10 = src[y1c*W1 + x0c], v11 = src[y1c*W1 + x1c];
    return (v00*(1.f-tx) + v01*tx)*(1.f-ty) + (v10*(1.f-tx) + v11*tx)*ty;
}

__global__ void bs2_kernel(const float* __restrict__ d1, const float* __restrict__ v1) {
    int p = blockIdx.x * blockDim.x + threadIdx.x;
    if (p >= HWS2) return;
    int h = p / W2, w = p % W2;
    float cd = resize2x_sample(d1, h, w);
    float cv = resize2x_sample(v1, h, w);
    float low  = -fminf(cd, cv);
    g_bs[p]        = cd + low + 1e-12f;
    g_bs[HWS2 + p] = (cv - low) / (float)(ND2 - 1);
}

// ---------------- projection helper ----------------
template<int H, int W>
__device__ __forceinline__ void project_offsets(
    const float* __restrict__ R, const float* __restrict__ T,
    float fx, float fy, float depth, int* off, float* wt) {
    float px = (R[0]*fx + R[1]*fy + R[2]) * depth + T[0];
    float py = (R[3]*fx + R[4]*fy + R[5]) * depth + T[1];
    float pz = (R[6]*fx + R[7]*fy + R[8]) * depth + T[2];
    float iz = __fdividef(1.0f, pz);
    float gx = px * iz / (0.5f*(float)(W-1)) - 1.0f;
    float gy = py * iz / (0.5f*(float)(H-1)) - 1.0f;
    float ix = ((gx + 1.0f)*(float)W - 1.0f) * 0.5f;
    float iy = ((gy + 1.0f)*(float)H - 1.0f) * 0.5f;
    ix = fminf(fmaxf(ix, -8.0f), (float)(W+8));
    iy = fminf(fmaxf(iy, -8.0f), (float)(H+8));
    float x0f = floorf(ix), y0f = floorf(iy);
    float tx = ix - x0f, ty = iy - y0f;
    int x0 = (int)x0f, y0 = (int)y0f;
    bool vx0 = (x0   >= 0) && (x0   <= W-1);
    bool vx1 = (x0+1 >= 0) && (x0+1 <= W-1);
    bool vy0 = (y0   >= 0) && (y0   <= H-1);
    bool vy1 = (y0+1 >= 0) && (y0+1 <= H-1);
    int x0c = min(max(x0,   0), W-1), x1c = min(max(x0+1, 0), W-1);
    int y0c = min(max(y0,   0), H-1), y1c = min(max(y0+1, 0), H-1);
    off[0] = y0c*W + x0c;  off[1] = y0c*W + x1c;
    off[2] = y1c*W + x0c;  off[3] = y1c*W + x1c;
    wt[0] = (vx0 && vy0) ? (1.f-tx)*(1.f-ty) : 0.f;
    wt[1] = (vx1 && vy0) ? tx*(1.f-ty)       : 0.f;
    wt[2] = (vx0 && vy1) ? (1.f-tx)*ty       : 0.f;
    wt[3] = (vx1 && vy1) ? tx*ty             : 0.f;
}

__device__ __forceinline__ float4 gather4(const float4* __restrict__ b,
                                          const int* off, const float* wt) {
    float4 p0 = b[off[0]], p1 = b[off[1]], p2 = b[off[2]], p3 = b[off[3]];
    float4 a;
    a.x = wt[0]*p0.x + wt[1]*p1.x + wt[2]*p2.x + wt[3]*p3.x;
    a.y = wt[0]*p0.y + wt[1]*p1.y + wt[2]*p2.y + wt[3]*p3.y;
    a.z = wt[0]*p0.z + wt[1]*p1.z + wt[2]*p2.z + wt[3]*p3.z;
    a.w = wt[0]*p0.w + wt[1]*p1.w + wt[2]*p2.w + wt[3]*p3.w;
    return a;
}

__device__ __forceinline__ float4 var3(float4 r, float4 a1, float4 a2) {
    float4 o;
    float s, q, m;
    s = r.x + a1.x + a2.x; q = r.x*r.x + a1.x*a1.x + a2.x*a2.x;
    m = s*(1.f/3.f); o.x = q*(1.f/3.f) - m*m;
    s = r.y + a1.y + a2.y; q = r.y*r.y + a1.y*a1.y + a2.y*a2.y;
    m = s*(1.f/3.f); o.y = q*(1.f/3.f) - m*m;
    s = r.z + a1.z + a2.z; q = r.z*r.z + a1.z*a1.z + a2.z*a2.z;
    m = s*(1.f/3.f); o.z = q*(1.f/3.f) - m*m;
    s = r.w + a1.w + a2.w; q = r.w*r.w + a1.w*a1.w + a2.w*a2.w;
    m = s*(1.f/3.f); o.w = q*(1.f/3.f) - m*m;
    return o;
}

// ---------------- pass1: depth-pair, SEQUENTIAL phase A, shared phase B ----------------
// Phase A0: project depth0, gather all CG groups -> var0[CG]; off/wt regs die.
// Phase A1: same for depth1 -> var1[CG].
// Phase B : 27 taps; each tap loads its weight float4s once (shared by both
//           depths), dots against var0/var1, stores immediately (2 live accs).
template<int C, int D, int H, int W, bool STAGE2>
__global__ void __launch_bounds__(128, 3)
pass1_kernel(const float* __restrict__ wconv,   // (C, 27)
             int stage) {
    constexpr int HW = H * W;
    constexpr int CG = C / 4;

    // transposed weights: sw[k*C + c] = wconv[c*27 + k], read as float4 over c
    __shared__ float sw[27 * C];
    for (int i = threadIdx.x; i < 27*C; i += blockDim.x) {
        int k = i / C, c = i % C;
        sw[i] = wconv[c*27 + k];
    }
    __syncthreads();
    const float4* swv = reinterpret_cast<const float4*>(sw);

    int idx = blockIdx.x * blockDim.x + threadIdx.x;
    if (idx >= (D/2) * HW) return;
    int hw = idx % HW;
    int dp = idx / HW;
    int d0 = 2*dp;
    int h = hw / W, w = hw % W;

    float base, step;
    if (STAGE2) { base = g_bs[hw]; step = g_bs[HWS2 + hw]; }
    else        { base = g_dmin;   step = g_dstep; }

    const float4* ft0 = g_ft + hw;
    const float4* ft1 = g_ft + (size_t)(1*CG) * HW;
    const float4* ft2 = g_ft + (size_t)(2*CG) * HW;
    float fx = (float)w, fy = (float)h;

    float4 var0[CG], var1[CG];

    // ---- phase A, depth 0 ----
    {
        float dep = fmaf(step, (float)d0, base);
        int   off[2][4];
        float wt[2][4];
        project_offsets<H, W>(g_rot[stage][0], g_trans[stage][0], fx, fy, dep, off[0], wt[0]);
        project_offsets<H, W>(g_rot[stage][1], g_trans[stage][1], fx, fy, dep, off[1], wt[1]);
        #pragma unroll
        for (int cg = 0; cg < CG; cg++) {
            float4 r4 = ft0[(size_t)cg * HW];
            var0[cg] = var3(r4, gather4(ft1 + (size_t)cg * HW, off[0], wt[0]),
                                gather4(ft2 + (size_t)cg * HW, off[1], wt[1]));
        }
    }

    // ---- phase A, depth 1 ----
    {
        float dep = fmaf(step, (float)(d0+1), base);
        int   off[2][4];
        float wt[2][4];
        project_offsets<H, W>(g_rot[stage][0], g_trans[stage][0], fx, fy, dep, off[0], wt[0]);
        project_offsets<H, W>(g_rot[stage][1], g_trans[stage][1], fx, fy, dep, off[1], wt[1]);
        #pragma unroll
        for (int cg = 0; cg < CG; cg++) {
            float4 r4 = ft0[(size_t)cg * HW];
            var1[cg] = var3(r4, gather4(ft1 + (size_t)cg * HW, off[0], wt[0]),
                                gather4(ft2 + (size_t)cg * HW, off[1], wt[1]));
        }
    }

    // ---- phase B: 27 tap-dots, store immediately ----
    float* out0 = g_G + (size_t)d0*HW + hw;
    float* out1 = out0 + HW;
    #pragma unroll
    for (int k = 0; k < 27; k++) {
        float s0 = 0.f, s1 = 0.f;
        #pragma unroll
        for (int cg = 0; cg < CG; cg++) {
            float4 wv = swv[k*CG + cg];
            s0 = fmaf(var0[cg].x, wv.x, s0);
            s0 = fmaf(var0[cg].y, wv.y, s0);
            s0 = fmaf(var0[cg].z, wv.z, s0);
            s0 = fmaf(var0[cg].w, wv.w, s0);
            s1 = fmaf(var1[cg].x, wv.x, s1);
            s1 = fmaf(var1[cg].y, wv.y, s1);
            s1 = fmaf(var1[cg].z, wv.z, s1);
            s1 = fmaf(var1[cg].w, wv.w, s1);
        }
        out0[(size_t)k*(D*HW)] = s0;
        out1[(size_t)k*(D*HW)] = s1;
    }
}

// ---------------- cost: 27-tap shifted-plane sum, 4 pixels per thread ----------------
template<int D, int H, int W>
__global__ void __launch_bounds__(256)
cost_kernel(const float* __restrict__ bias) {
    constexpr int HW = H * W;
    constexpr int W4 = W / 4;
    int t = blockIdx.x * blockDim.x + threadIdx.x;
    if (t >= D * H * W4) return;
    int wq = (t % W4) * 4;
    int r  = t / W4;
    int h = r % H;
    int d = r / H;

    float bb = bias[0];
    float4 s = make_float4(bb, bb, bb, bb);

    #pragma unroll
    for (int kd = 0; kd < 3; kd++) {
        int dd = d + kd - 1;
        if (dd < 0 || dd >= D) continue;
        #pragma unroll
        for (int kh = 0; kh < 3; kh++) {
            int hh = h + kh - 1;
            if (hh < 0 || hh >= H) continue;
            #pragma unroll
            for (int kw = 0; kw < 3; kw++) {
                const float* row = g_G + (size_t)(kd*9 + kh*3 + kw)*(D*HW)
                                       + (size_t)dd*HW + (size_t)hh*W;
                float4 v = *reinterpret_cast<const float4*>(row + wq);
                if (kw == 0) {          // shift -1
                    float left = (wq > 0) ? row[wq-1] : 0.f;
                    s.x += left; s.y += v.x; s.z += v.y; s.w += v.z;
                } else if (kw == 1) {   // shift 0
                    s.x += v.x; s.y += v.y; s.z += v.z; s.w += v.w;
                } else {                // shift +1
                    float right = (wq + 4 < W) ? row[wq+4] : 0.f;
                    s.x += v.y; s.y += v.z; s.z += v.w; s.w += right;
                }
            }
        }
    }
    *reinterpret_cast<float4*>(g_cost + (size_t)d*HW + (size_t)h*W + wq) = s;
}

// ---------------- per-pixel epilogue ----------------
template<int D, int H, int W, bool STAGE2>
__global__ void __launch_bounds__(256)
pixel_kernel(float* __restrict__ outd,
             float* __restrict__ outc,
             float* __restrict__ outv) {
    constexpr int HW = H * W;
    int p = blockIdx.x * blockDim.x + threadIdx.x;
    if (p >= HW) return;

    float e[D];
    float mx = -1e30f;
    #pragma unroll
    for (int d = 0; d < D; d++) { e[d] = g_cost[(size_t)d*HW + p]; mx = fmaxf(mx, e[d]); }
    float sum = 0.f;
    #pragma unroll
    for (int d = 0; d < D; d++) { e[d] = expf(e[d] - mx); sum += e[d]; }
    float inv = 1.0f / sum;
    float m1 = 0.f;
    #pragma unroll
    for (int d = 0; d < D; d++) {
        float pr = e[d] * inv;
        e[d] = pr;
        m1 += pr * (float)d;
    }

    float base, step;
    if (STAGE2) { base = g_bs[p]; step = g_bs[HWS2 + p]; }
    else        { base = g_dmin; step = g_dstep; }

    float depth = fmaf(step, m1, base);
    float var = 0.f;
    #pragma unroll
    for (int d = 0; d < D; d++) {
        float t = step * ((float)d - m1);
        var += e[d] * t * t;
    }
    int di = min(max((int)m1, 0), D-1);
    float conf = 0.f;
    #pragma unroll
    for (int d = 0; d < D; d++)
        if (d >= di-1 && d <= di+2) conf += e[d];

    outd[p] = depth;
    outc[p] = conf;
    outv[p] = 1.5f * sqrtf(fmaxf(var, 0.f));
}

// ---------------- launch ----------------
extern "C" void kernel_launch(void* const* d_in, const int* in_sizes, int n_in,
                              void* d_out, int out_size) {
    const float* feats1 = (const float*)d_in[0];
    const float* feats2 = (const float*)d_in[1];
    const float* proj1  = (const float*)d_in[2];
    const float* proj2  = (const float*)d_in[3];
    const float* depthv = (const float*)d_in[4];
    const float* w1     = (const float*)d_in[6];
    const float* b1     = (const float*)d_in[7];
    const float* w2     = (const float*)d_in[8];
    const float* b2     = (const float*)d_in[9];

    float* out = (float*)d_out;
    float* o_d1 = out;
    float* o_c1 = out + HWS1;
    float* o_v1 = out + 2*HWS1;
    float* o_d2 = out + 3*HWS1;
    float* o_c2 = out + 3*HWS1 + HWS2;
    float* o_v2 = out + 3*HWS1 + 2*HWS2;

    setup_kernel<<<1, 1>>>(proj1, proj2, depthv);                             // 1
    transpose_kernel<C1, HWS1><<<(3*(C1/4)*HWS1 + 255)/256, 256>>>(feats1);   // 2
    pad_kernel<<<1, 32>>>(0);                                                  // 3

    // ---- stage 1 (C=32, D=48, 128x160) ----
    {
        int nthr = (ND1/2) * HWS1;   // 491520
        pass1_kernel<C1, ND1, H1, W1, false>                                   // 4 (profiled)
            <<<(nthr + 127)/128, 128>>>(w1, 0);
        cost_kernel<ND1, H1, W1>
            <<<(ND1*H1*(W1/4) + 255)/256, 256>>>(b1);
        pixel_kernel<ND1, H1, W1, false>
            <<<(HWS1 + 255)/256, 256>>>(o_d1, o_c1, o_v1);
    }

    // ---- stage 2 (C=16, D=8, 256x320) ----
    {
        int nthr = (ND2/2) * HWS2;   // 327680
        transpose_kernel<C2, HWS2><<<(3*(C2/4)*HWS2 + 255)/256, 256>>>(feats2);
        bs2_kernel<<<(HWS2 + 255)/256, 256>>>(o_d1, o_v1);
        pass1_kernel<C2, ND2, H2, W2, true>
            <<<(nthr + 127)/128, 128>>>(w2, 1);
        cost_kernel<ND2, H2, W2>
            <<<(ND2*H2*(W2/4) + 255)/256, 256>>>(b2);
        pixel_kernel<ND2, H2, W2, true>
            <<<(HWS2 + 255)/256, 256>>>(o_d2, o_c2, o_v2);
    }
}

// round 13
// speedup vs baseline: 1.2701x; 1.2561x over previous
#include <cuda_runtime.h>
#include <math.h>

// ---------------- problem constants ----------------
#define H1 128
#define W1 160
#define H2 256
#define W2 320
#define HWS1 (H1*W1)   // 20480
#define HWS2 (H2*W2)   // 81920
#define ND1 48
#define ND2 8
#define C1 32
#define C2 16

// ---------------- scratch (device globals; no allocation allowed) ----------------
__device__ float g_rot[2][2][9];
__device__ float g_trans[2][2][3];
__device__ float g_dmin, g_dstep;
__device__ float g_pad[32];

// per-channel-group variance planes: g_V[cg][d*HW+hw] (float4 per entry)
// stage1: 8 * 48 * 20480 = 7.86M float4 (126 MB); stage2 (4*8*81920) fits.
__device__ float4 g_V[8 * ND1 * HWS1];
// 27 channel-reduced conv planes. stage1: 27*48*20480 floats (106MB). stage2 fits.
__device__ float g_G[27 * ND1 * HWS1];
__device__ float g_cost[ND1 * HWS1];       // stage2: 8*81920 fits
__device__ float g_bs[2 * HWS2];           // stage-2 per-pixel depth base/step
// channel-interleaved features: (3, C/4, HW) of float4
__device__ float4 g_ft[3 * (C2/4) * HWS2];

// ---------------- f32x2 packed math (sm_103a FFMA2 via PTX) ----------------
__device__ __forceinline__ unsigned long long pk2(float a, float b) {
    unsigned long long r;
    asm("mov.b64 %0, {%1, %2};" : "=l"(r) : "f"(a), "f"(b));
    return r;
}
__device__ __forceinline__ void fma2(unsigned long long& d,
                                     unsigned long long a, unsigned long long b) {
    asm("fma.rn.f32x2 %0, %1, %2, %0;" : "+l"(d) : "l"(a), "l"(b));
}
__device__ __forceinline__ float upk2_sum(unsigned long long v) {
    float x, y;
    asm("mov.b64 {%0, %1}, %2;" : "=f"(x), "=f"(y) : "l"(v));
    return x + y;
}

// ---------------- setup ----------------
__device__ void mat4_inv_d(const double* M, double* out) {
    double a[4][8];
    for (int i = 0; i < 4; i++)
        for (int j = 0; j < 4; j++) { a[i][j] = M[i*4+j]; a[i][j+4] = (i==j) ? 1.0 : 0.0; }
    for (int col = 0; col < 4; col++) {
        int piv = col; double best = fabs(a[col][col]);
        for (int r = col+1; r < 4; r++) if (fabs(a[r][col]) > best) { best = fabs(a[r][col]); piv = r; }
        if (piv != col) for (int j = 0; j < 8; j++) { double t = a[col][j]; a[col][j] = a[piv][j]; a[piv][j] = t; }
        double d = a[col][col];
        for (int j = 0; j < 8; j++) a[col][j] /= d;
        for (int r = 0; r < 4; r++) if (r != col) {
            double f = a[r][col];
            for (int j = 0; j < 8; j++) a[r][j] -= f * a[col][j];
        }
    }
    for (int i = 0; i < 4; i++) for (int j = 0; j < 4; j++) out[i*4+j] = a[i][j+4];
}

__global__ void setup_kernel(const float* __restrict__ proj1,
                             const float* __restrict__ proj2,
                             const float* __restrict__ depthv) {
    if (threadIdx.x != 0 || blockIdx.x != 0) return;
    for (int s = 0; s < 2; s++) {
        const float* P = s ? proj2 : proj1;   // (3 views, 2, 4, 4)
        double comp[3][16];
        for (int v = 0; v < 3; v++) {
            const float* E   = P + v*32;
            const float* Kin = P + v*32 + 16;
            for (int i = 0; i < 16; i++) comp[v][i] = (double)E[i];
            for (int i = 0; i < 3; i++)
                for (int j = 0; j < 4; j++) {
                    double t = 0.0;
                    for (int k = 0; k < 3; k++) t += (double)Kin[i*4+k] * (double)E[k*4+j];
                    comp[v][i*4+j] = t;
                }
        }
        double inv[16];
        mat4_inv_d(comp[0], inv);
        for (int v = 1; v < 3; v++) {
            double R[16];
            for (int i = 0; i < 4; i++)
                for (int j = 0; j < 4; j++) {
                    double t = 0.0;
                    for (int k = 0; k < 4; k++) t += comp[v][i*4+k] * inv[k*4+j];
                    R[i*4+j] = t;
                }
            for (int i = 0; i < 3; i++) {
                for (int j = 0; j < 3; j++) g_rot[s][v-1][i*3+j] = (float)R[i*4+j];
                g_trans[s][v-1][i] = (float)R[i*4+3];
            }
        }
    }
    g_dmin  = depthv[0];
    g_dstep = (depthv[ND1-1] - depthv[0]) / (float)(ND1 - 1);
}

__global__ void pad_kernel(int v) {
    if (blockIdx.x == 0 && threadIdx.x == 0) g_pad[v] = (float)v;
}

// ---------------- feature transpose: (3,C,H,W) -> (3,C/4,HW) of float4 ----------------
template<int C, int HW>
__global__ void __launch_bounds__(256)
transpose_kernel(const float* __restrict__ feats) {
    int i = blockIdx.x * blockDim.x + threadIdx.x;
    if (i >= 3 * (C/4) * HW) return;
    int hw = i % HW;
    int t  = i / HW;
    int cg = t % (C/4);
    int v  = t / (C/4);
    const float* src = feats + ((size_t)(v*C + cg*4)) * HW + hw;
    float4 val;
    val.x = src[0];
    val.y = src[HW];
    val.z = src[2*(size_t)HW];
    val.w = src[3*(size_t)HW];
    g_ft[i] = val;
}

// ---------------- 2x bilinear upsample sample ----------------
__device__ __forceinline__ float resize2x_sample(const float* __restrict__ src, int h, int w) {
    float fy = 0.5f * (float)h - 0.25f;
    float fx = 0.5f * (float)w - 0.25f;
    float y0f = floorf(fy), x0f = floorf(fx);
    float ty = fy - y0f, tx = fx - x0f;
    int y0 = (int)y0f, x0 = (int)x0f;
    int y0c = min(max(y0, 0), H1-1), y1c = min(max(y0+1, 0), H1-1);
    int x0c = min(max(x0, 0), W1-1), x1c = min(max(x0+1, 0), W1-1);
    float v00 = src[y0c*W1 + x0c], v01 = src[y0c*W1 + x1c];
    float v10 = src[y1c*W1 + x0c], v11 = src[y1c*W1 + x1c];
    return (v00*(1.f-tx) + v01*tx)*(1.f-ty) + (v10*(1.f-tx) + v11*tx)*ty;
}

__global__ void bs2_kernel(const float* __restrict__ d1, const float* __restrict__ v1) {
    int p = blockIdx.x * blockDim.x + threadIdx.x;
    if (p >= HWS2) return;
    int h = p / W2, w = p % W2;
    float cd = resize2x_sample(d1, h, w);
    float cv = resize2x_sample(v1, h, w);
    float low  = -fminf(cd, cv);
    g_bs[p]        = cd + low + 1e-12f;
    g_bs[HWS2 + p] = (cv - low) / (float)(ND2 - 1);
}

// ---------------- projection helper ----------------
template<int H, int W>
__device__ __forceinline__ void project_offsets(
    const float* __restrict__ R, const float* __restrict__ T,
    float fx, float fy, float depth, int* off, float* wt) {
    float px = (R[0]*fx + R[1]*fy + R[2]) * depth + T[0];
    float py = (R[3]*fx + R[4]*fy + R[5]) * depth + T[1];
    float pz = (R[6]*fx + R[7]*fy + R[8]) * depth + T[2];
    float iz = __fdividef(1.0f, pz);
    float gx = px * iz / (0.5f*(float)(W-1)) - 1.0f;
    float gy = py * iz / (0.5f*(float)(H-1)) - 1.0f;
    float ix = ((gx + 1.0f)*(float)W - 1.0f) * 0.5f;
    float iy = ((gy + 1.0f)*(float)H - 1.0f) * 0.5f;
    ix = fminf(fmaxf(ix, -8.0f), (float)(W+8));
    iy = fminf(fmaxf(iy, -8.0f), (float)(H+8));
    float x0f = floorf(ix), y0f = floorf(iy);
    float tx = ix - x0f, ty = iy - y0f;
    int x0 = (int)x0f, y0 = (int)y0f;
    bool vx0 = (x0   >= 0) && (x0   <= W-1);
    bool vx1 = (x0+1 >= 0) && (x0+1 <= W-1);
    bool vy0 = (y0   >= 0) && (y0   <= H-1);
    bool vy1 = (y0+1 >= 0) && (y0+1 <= H-1);
    int x0c = min(max(x0,   0), W-1), x1c = min(max(x0+1, 0), W-1);
    int y0c = min(max(y0,   0), H-1), y1c = min(max(y0+1, 0), H-1);
    off[0] = y0c*W + x0c;  off[1] = y0c*W + x1c;
    off[2] = y1c*W + x0c;  off[3] = y1c*W + x1c;
    wt[0] = (vx0 && vy0) ? (1.f-tx)*(1.f-ty) : 0.f;
    wt[1] = (vx1 && vy0) ? tx*(1.f-ty)       : 0.f;
    wt[2] = (vx0 && vy1) ? (1.f-tx)*ty       : 0.f;
    wt[3] = (vx1 && vy1) ? tx*ty             : 0.f;
}

__device__ __forceinline__ float4 gather4(const float4* __restrict__ b,
                                          const int* off, const float* wt) {
    float4 p0 = b[off[0]], p1 = b[off[1]], p2 = b[off[2]], p3 = b[off[3]];
    float4 a;
    a.x = wt[0]*p0.x + wt[1]*p1.x + wt[2]*p2.x + wt[3]*p3.x;
    a.y = wt[0]*p0.y + wt[1]*p1.y + wt[2]*p2.y + wt[3]*p3.y;
    a.z = wt[0]*p0.z + wt[1]*p1.z + wt[2]*p2.z + wt[3]*p3.z;
    a.w = wt[0]*p0.w + wt[1]*p1.w + wt[2]*p2.w + wt[3]*p3.w;
    return a;
}

__device__ __forceinline__ float4 var3(float4 r, float4 a1, float4 a2) {
    float4 o;
    float s, q, m;
    s = r.x + a1.x + a2.x; q = r.x*r.x + a1.x*a1.x + a2.x*a2.x;
    m = s*(1.f/3.f); o.x = q*(1.f/3.f) - m*m;
    s = r.y + a1.y + a2.y; q = r.y*r.y + a1.y*a1.y + a2.y*a2.y;
    m = s*(1.f/3.f); o.y = q*(1.f/3.f) - m*m;
    s = r.z + a1.z + a2.z; q = r.z*r.z + a1.z*a1.z + a2.z*a2.z;
    m = s*(1.f/3.f); o.z = q*(1.f/3.f) - m*m;
    s = r.w + a1.w + a2.w; q = r.w*r.w + a1.w*a1.w + a2.w*a2.w;
    m = s*(1.f/3.f); o.w = q*(1.f/3.f) - m*m;
    return o;
}

// ---------------- var kernel: gather machine only (no weights, no acc arrays) ----------------
// Thread handles depth-pair (dp, dp+D/2) at one pixel; ref loads shared.
// Streams per-cg variance straight to g_V -> tiny live state, high occupancy.
template<int C, int D, int H, int W, bool STAGE2>
__global__ void __launch_bounds__(256)
var_kernel(int stage) {
    constexpr int HW = H * W;
    constexpr int CG = C / 4;
    constexpr int DHW = D * HW;

    int idx = blockIdx.x * blockDim.x + threadIdx.x;
    if (idx >= (D/2) * HW) return;
    int hw = idx % HW;
    int dp = idx / HW;
    int h = hw / W, w = hw % W;

    float base, step;
    if (STAGE2) { base = g_bs[hw]; step = g_bs[HWS2 + hw]; }
    else        { base = g_dmin;   step = g_dstep; }
    float dep0 = fmaf(step, (float)dp,         base);
    float dep1 = fmaf(step, (float)(dp + D/2), base);

    int   off[2][2][4];   // [depth][view][corner]
    float wt[2][2][4];
    float fx = (float)w, fy = (float)h;
    project_offsets<H, W>(g_rot[stage][0], g_trans[stage][0], fx, fy, dep0, off[0][0], wt[0][0]);
    project_offsets<H, W>(g_rot[stage][1], g_trans[stage][1], fx, fy, dep0, off[0][1], wt[0][1]);
    project_offsets<H, W>(g_rot[stage][0], g_trans[stage][0], fx, fy, dep1, off[1][0], wt[1][0]);
    project_offsets<H, W>(g_rot[stage][1], g_trans[stage][1], fx, fy, dep1, off[1][1], wt[1][1]);

    const float4* ft0 = g_ft + hw;
    const float4* ft1 = g_ft + (size_t)(1*CG) * HW;
    const float4* ft2 = g_ft + (size_t)(2*CG) * HW;

    int t0 = dp*HW + hw;            // voxel index for depth dp
    int t1 = t0 + (D/2)*HW;         // voxel index for depth dp+D/2

    #pragma unroll
    for (int cg = 0; cg < CG; cg++) {
        float4 r4 = ft0[(size_t)cg * HW];                // shared across pair
        const float4* b1 = ft1 + (size_t)cg * HW;
        const float4* b2 = ft2 + (size_t)cg * HW;
        float4 v0 = var3(r4, gather4(b1, off[0][0], wt[0][0]),
                             gather4(b2, off[0][1], wt[0][1]));
        float4 v1 = var3(r4, gather4(b1, off[1][0], wt[1][0]),
                             gather4(b2, off[1][1], wt[1][1]));
        g_V[(size_t)cg*DHW + t0] = v0;
        g_V[(size_t)cg*DHW + t1] = v1;
    }
}

// ---------------- tap kernel: dense FMA machine (f32x2), 2 voxels/thread ----------------
// G[k][vox] = sum_c var[c][vox] * w[c][k]; weights packed as f32-pairs in smem,
// shared across the 2 voxels; FFMA2 halves FMA issue count.
template<int C, int D, int H, int W>
__global__ void __launch_bounds__(256)
tap_kernel(const float* __restrict__ wconv) {   // (C, 27)
    constexpr int HW  = H * W;
    constexpr int CG  = C / 4;
    constexpr int DHW = D * HW;
    constexpr int HALF = (D/2) * HW;

    __shared__ ulonglong2 swp[27 * CG];   // swp[k*CG+cg] = {(w[4cg],w[4cg+1]),(w[4cg+2],w[4cg+3])} at tap k
    for (int i = threadIdx.x; i < 27*CG; i += blockDim.x) {
        int k = i / CG, cg = i % CG;
        ulonglong2 e;
        e.x = pk2(wconv[(4*cg + 0)*27 + k], wconv[(4*cg + 1)*27 + k]);
        e.y = pk2(wconv[(4*cg + 2)*27 + k], wconv[(4*cg + 3)*27 + k]);
        swp[i] = e;
    }
    __syncthreads();

    int t = blockIdx.x * blockDim.x + threadIdx.x;
    if (t >= HALF) return;

    ulonglong2 va[CG], vb[CG];
    #pragma unroll
    for (int cg = 0; cg < CG; cg++) {
        va[cg] = *reinterpret_cast<const ulonglong2*>(&g_V[(size_t)cg*DHW + t]);
        vb[cg] = *reinterpret_cast<const ulonglong2*>(&g_V[(size_t)cg*DHW + t + HALF]);
    }

    #pragma unroll
    for (int k = 0; k < 27; k++) {
        unsigned long long accA = 0ULL, accB = 0ULL;
        #pragma unroll
        for (int cg = 0; cg < CG; cg++) {
            ulonglong2 wv = swp[k*CG + cg];
            fma2(accA, va[cg].x, wv.x);
            fma2(accA, va[cg].y, wv.y);
            fma2(accB, vb[cg].x, wv.x);
            fma2(accB, vb[cg].y, wv.y);
        }
        g_G[(size_t)k*DHW + t]        = upk2_sum(accA);
        g_G[(size_t)k*DHW + t + HALF] = upk2_sum(accB);
    }
}

// ---------------- cost: 27-tap shifted-plane sum, 4 pixels per thread ----------------
template<int D, int H, int W>
__global__ void __launch_bounds__(256)
cost_kernel(const float* __restrict__ bias) {
    constexpr int HW = H * W;
    constexpr int W4 = W / 4;
    int t = blockIdx.x * blockDim.x + threadIdx.x;
    if (t >= D * H * W4) return;
    int wq = (t % W4) * 4;
    int r  = t / W4;
    int h = r % H;
    int d = r / H;

    float bb = bias[0];
    float4 s = make_float4(bb, bb, bb, bb);

    #pragma unroll
    for (int kd = 0; kd < 3; kd++) {
        int dd = d + kd - 1;
        if (dd < 0 || dd >= D) continue;
        #pragma unroll
        for (int kh = 0; kh < 3; kh++) {
            int hh = h + kh - 1;
            if (hh < 0 || hh >= H) continue;
            #pragma unroll
            for (int kw = 0; kw < 3; kw++) {
                const float* row = g_G + (size_t)(kd*9 + kh*3 + kw)*(D*HW)
                                       + (size_t)dd*HW + (size_t)hh*W;
                float4 v = *reinterpret_cast<const float4*>(row + wq);
                if (kw == 0) {          // shift -1
                    float left = (wq > 0) ? row[wq-1] : 0.f;
                    s.x += left; s.y += v.x; s.z += v.y; s.w += v.z;
                } else if (kw == 1) {   // shift 0
                    s.x += v.x; s.y += v.y; s.z += v.z; s.w += v.w;
                } else {                // shift +1
                    float right = (wq + 4 < W) ? row[wq+4] : 0.f;
                    s.x += v.y; s.y += v.z; s.z += v.w; s.w += right;
                }
            }
        }
    }
    *reinterpret_cast<float4*>(g_cost + (size_t)d*HW + (size_t)h*W + wq) = s;
}

// ---------------- per-pixel epilogue ----------------
template<int D, int H, int W, bool STAGE2>
__global__ void __launch_bounds__(256)
pixel_kernel(float* __restrict__ outd,
             float* __restrict__ outc,
             float* __restrict__ outv) {
    constexpr int HW = H * W;
    int p = blockIdx.x * blockDim.x + threadIdx.x;
    if (p >= HW) return;

    float e[D];
    float mx = -1e30f;
    #pragma unroll
    for (int d = 0; d < D; d++) { e[d] = g_cost[(size_t)d*HW + p]; mx = fmaxf(mx, e[d]); }
    float sum = 0.f;
    #pragma unroll
    for (int d = 0; d < D; d++) { e[d] = expf(e[d] - mx); sum += e[d]; }
    float inv = 1.0f / sum;
    float m1 = 0.f;
    #pragma unroll
    for (int d = 0; d < D; d++) {
        float pr = e[d] * inv;
        e[d] = pr;
        m1 += pr * (float)d;
    }

    float base, step;
    if (STAGE2) { base = g_bs[p]; step = g_bs[HWS2 + p]; }
    else        { base = g_dmin; step = g_dstep; }

    float depth = fmaf(step, m1, base);
    float var = 0.f;
    #pragma unroll
    for (int d = 0; d < D; d++) {
        float t = step * ((float)d - m1);
        var += e[d] * t * t;
    }
    int di = min(max((int)m1, 0), D-1);
    float conf = 0.f;
    #pragma unroll
    for (int d = 0; d < D; d++)
        if (d >= di-1 && d <= di+2) conf += e[d];

    outd[p] = depth;
    outc[p] = conf;
    outv[p] = 1.5f * sqrtf(fmaxf(var, 0.f));
}

// ---------------- launch ----------------
extern "C" void kernel_launch(void* const* d_in, const int* in_sizes, int n_in,
                              void* d_out, int out_size) {
    const float* feats1 = (const float*)d_in[0];
    const float* feats2 = (const float*)d_in[1];
    const float* proj1  = (const float*)d_in[2];
    const float* proj2  = (const float*)d_in[3];
    const float* depthv = (const float*)d_in[4];
    const float* w1     = (const float*)d_in[6];
    const float* b1     = (const float*)d_in[7];
    const float* w2     = (const float*)d_in[8];
    const float* b2     = (const float*)d_in[9];

    float* out = (float*)d_out;
    float* o_d1 = out;
    float* o_c1 = out + HWS1;
    float* o_v1 = out + 2*HWS1;
    float* o_d2 = out + 3*HWS1;
    float* o_c2 = out + 3*HWS1 + HWS2;
    float* o_v2 = out + 3*HWS1 + 2*HWS2;

    setup_kernel<<<1, 1>>>(proj1, proj2, depthv);                             // 1
    transpose_kernel<C1, HWS1><<<(3*(C1/4)*HWS1 + 255)/256, 256>>>(feats1);   // 2
    pad_kernel<<<1, 32>>>(0);                                                  // 3

    // ---- stage 1 (C=32, D=48, 128x160) ----
    {
        int nhalf = (ND1/2) * HWS1;   // 491520
        var_kernel<C1, ND1, H1, W1, false>                                     // 4 (profiled)
            <<<(nhalf + 255)/256, 256>>>(0);
        tap_kernel<C1, ND1, H1, W1>
            <<<(nhalf + 255)/256, 256>>>(w1);
        cost_kernel<ND1, H1, W1>
            <<<(ND1*H1*(W1/4) + 255)/256, 256>>>(b1);
        pixel_kernel<ND1, H1, W1, false>
            <<<(HWS1 + 255)/256, 256>>>(o_d1, o_c1, o_v1);
    }

    // ---- stage 2 (C=16, D=8, 256x320) ----
    {
        int nhalf = (ND2/2) * HWS2;   // 327680
        transpose_kernel<C2, HWS2><<<(3*(C2/4)*HWS2 + 255)/256, 256>>>(feats2);
        bs2_kernel<<<(HWS2 + 255)/256, 256>>>(o_d1, o_v1);
        var_kernel<C2, ND2, H2, W2, true>
            <<<(nhalf + 255)/256, 256>>>(1);
        tap_kernel<C2, ND2, H2, W2>
            <<<(nhalf + 255)/256, 256>>>(w2);
        cost_kernel<ND2, H2, W2>
            <<<(ND2*H2*(W2/4) + 255)/256, 256>>>(b2);
        pixel_kernel<ND2, H2, W2, true>
            <<<(HWS2 + 255)/256, 256>>>(o_d2, o_c2, o_v2);
    }
}

// round 14
// speedup vs baseline: 1.3815x; 1.0877x over previous
#include <cuda_runtime.h>
#include <math.h>

// ---------------- problem constants ----------------
#define H1 128
#define W1 160
#define H2 256
#define W2 320
#define HWS1 (H1*W1)   // 20480
#define HWS2 (H2*W2)   // 81920
#define ND1 48
#define ND2 8
#define C1 32
#define C2 16

// ---------------- scratch (device globals; no allocation allowed) ----------------
__device__ float g_rot[2][2][9];
__device__ float g_trans[2][2][3];
__device__ float g_dmin, g_dstep;
__device__ float g_pad[32];

// per-channel-group variance planes: g_V[cg][d*HW+hw] (float4 per entry)
// stage1: 8 * 48 * 20480 = 7.86M float4 (126 MB); stage2 (4*8*81920) fits.
__device__ float4 g_V[8 * ND1 * HWS1];
// 9 depth-folded conv planes (fits in the old 27-plane buffer easily)
__device__ float g_B[9 * ND1 * HWS1];
__device__ float g_cost[ND1 * HWS1];       // stage2: 8*81920 fits
__device__ float g_bs[2 * HWS2];           // stage-2 per-pixel depth base/step
// channel-interleaved features: (3, C/4, HW) of float4
__device__ float4 g_ft[3 * (C2/4) * HWS2];

// ---------------- f32x2 packed math (sm_103a FFMA2 via PTX) ----------------
__device__ __forceinline__ unsigned long long pk2(float a, float b) {
    unsigned long long r;
    asm("mov.b64 %0, {%1, %2};" : "=l"(r) : "f"(a), "f"(b));
    return r;
}
__device__ __forceinline__ void fma2(unsigned long long& d,
                                     unsigned long long a, unsigned long long b) {
    asm("fma.rn.f32x2 %0, %1, %2, %0;" : "+l"(d) : "l"(a), "l"(b));
}
__device__ __forceinline__ float upk2_sum(unsigned long long v) {
    float x, y;
    asm("mov.b64 {%0, %1}, %2;" : "=f"(x), "=f"(y) : "l"(v));
    return x + y;
}

// ---------------- setup ----------------
__device__ void mat4_inv_d(const double* M, double* out) {
    double a[4][8];
    for (int i = 0; i < 4; i++)
        for (int j = 0; j < 4; j++) { a[i][j] = M[i*4+j]; a[i][j+4] = (i==j) ? 1.0 : 0.0; }
    for (int col = 0; col < 4; col++) {
        int piv = col; double best = fabs(a[col][col]);
        for (int r = col+1; r < 4; r++) if (fabs(a[r][col]) > best) { best = fabs(a[r][col]); piv = r; }
        if (piv != col) for (int j = 0; j < 8; j++) { double t = a[col][j]; a[col][j] = a[piv][j]; a[piv][j] = t; }
        double d = a[col][col];
        for (int j = 0; j < 8; j++) a[col][j] /= d;
        for (int r = 0; r < 4; r++) if (r != col) {
            double f = a[r][col];
            for (int j = 0; j < 8; j++) a[r][j] -= f * a[col][j];
        }
    }
    for (int i = 0; i < 4; i++) for (int j = 0; j < 4; j++) out[i*4+j] = a[i][j+4];
}

__global__ void setup_kernel(const float* __restrict__ proj1,
                             const float* __restrict__ proj2,
                             const float* __restrict__ depthv) {
    if (threadIdx.x != 0 || blockIdx.x != 0) return;
    for (int s = 0; s < 2; s++) {
        const float* P = s ? proj2 : proj1;   // (3 views, 2, 4, 4)
        double comp[3][16];
        for (int v = 0; v < 3; v++) {
            const float* E   = P + v*32;
            const float* Kin = P + v*32 + 16;
            for (int i = 0; i < 16; i++) comp[v][i] = (double)E[i];
            for (int i = 0; i < 3; i++)
                for (int j = 0; j < 4; j++) {
                    double t = 0.0;
                    for (int k = 0; k < 3; k++) t += (double)Kin[i*4+k] * (double)E[k*4+j];
                    comp[v][i*4+j] = t;
                }
        }
        double inv[16];
        mat4_inv_d(comp[0], inv);
        for (int v = 1; v < 3; v++) {
            double R[16];
            for (int i = 0; i < 4; i++)
                for (int j = 0; j < 4; j++) {
                    double t = 0.0;
                    for (int k = 0; k < 4; k++) t += comp[v][i*4+k] * inv[k*4+j];
                    R[i*4+j] = t;
                }
            for (int i = 0; i < 3; i++) {
                for (int j = 0; j < 3; j++) g_rot[s][v-1][i*3+j] = (float)R[i*4+j];
                g_trans[s][v-1][i] = (float)R[i*4+3];
            }
        }
    }
    g_dmin  = depthv[0];
    g_dstep = (depthv[ND1-1] - depthv[0]) / (float)(ND1 - 1);
}

__global__ void pad_kernel(int v) {
    if (blockIdx.x == 0 && threadIdx.x == 0) g_pad[v] = (float)v;
}

// ---------------- feature transpose: (3,C,H,W) -> (3,C/4,HW) of float4 ----------------
template<int C, int HW>
__global__ void __launch_bounds__(256)
transpose_kernel(const float* __restrict__ feats) {
    int i = blockIdx.x * blockDim.x + threadIdx.x;
    if (i >= 3 * (C/4) * HW) return;
    int hw = i % HW;
    int t  = i / HW;
    int cg = t % (C/4);
    int v  = t / (C/4);
    const float* src = feats + ((size_t)(v*C + cg*4)) * HW + hw;
    float4 val;
    val.x = src[0];
    val.y = src[HW];
    val.z = src[2*(size_t)HW];
    val.w = src[3*(size_t)HW];
    g_ft[i] = val;
}

// ---------------- 2x bilinear upsample sample ----------------
__device__ __forceinline__ float resize2x_sample(const float* __restrict__ src, int h, int w) {
    float fy = 0.5f * (float)h - 0.25f;
    float fx = 0.5f * (float)w - 0.25f;
    float y0f = floorf(fy), x0f = floorf(fx);
    float ty = fy - y0f, tx = fx - x0f;
    int y0 = (int)y0f, x0 = (int)x0f;
    int y0c = min(max(y0, 0), H1-1), y1c = min(max(y0+1, 0), H1-1);
    int x0c = min(max(x0, 0), W1-1), x1c = min(max(x0+1, 0), W1-1);
    float v00 = src[y0c*W1 + x0c], v01 = src[y0c*W1 + x1c];
    float v10 = src[y1c*W1 + x0c], v11 = src[y1c*W1 + x1c];
    return (v00*(1.f-tx) + v01*tx)*(1.f-ty) + (v10*(1.f-tx) + v11*tx)*ty;
}

__global__ void bs2_kernel(const float* __restrict__ d1, const float* __restrict__ v1) {
    int p = blockIdx.x * blockDim.x + threadIdx.x;
    if (p >= HWS2) return;
    int h = p / W2, w = p % W2;
    float cd = resize2x_sample(d1, h, w);
    float cv = resize2x_sample(v1, h, w);
    float low  = -fminf(cd, cv);
    g_bs[p]        = cd + low + 1e-12f;
    g_bs[HWS2 + p] = (cv - low) / (float)(ND2 - 1);
}

// ---------------- projection helper ----------------
template<int H, int W>
__device__ __forceinline__ void project_offsets(
    const float* __restrict__ R, const float* __restrict__ T,
    float fx, float fy, float depth, int* off, float* wt) {
    float px = (R[0]*fx + R[1]*fy + R[2]) * depth + T[0];
    float py = (R[3]*fx + R[4]*fy + R[5]) * depth + T[1];
    float pz = (R[6]*fx + R[7]*fy + R[8]) * depth + T[2];
    float iz = __fdividef(1.0f, pz);
    float gx = px * iz / (0.5f*(float)(W-1)) - 1.0f;
    float gy = py * iz / (0.5f*(float)(H-1)) - 1.0f;
    float ix = ((gx + 1.0f)*(float)W - 1.0f) * 0.5f;
    float iy = ((gy + 1.0f)*(float)H - 1.0f) * 0.5f;
    ix = fminf(fmaxf(ix, -8.0f), (float)(W+8));
    iy = fminf(fmaxf(iy, -8.0f), (float)(H+8));
    float x0f = floorf(ix), y0f = floorf(iy);
    float tx = ix - x0f, ty = iy - y0f;
    int x0 = (int)x0f, y0 = (int)y0f;
    bool vx0 = (x0   >= 0) && (x0   <= W-1);
    bool vx1 = (x0+1 >= 0) && (x0+1 <= W-1);
    bool vy0 = (y0   >= 0) && (y0   <= H-1);
    bool vy1 = (y0+1 >= 0) && (y0+1 <= H-1);
    int x0c = min(max(x0,   0), W-1), x1c = min(max(x0+1, 0), W-1);
    int y0c = min(max(y0,   0), H-1), y1c = min(max(y0+1, 0), H-1);
    off[0] = y0c*W + x0c;  off[1] = y0c*W + x1c;
    off[2] = y1c*W + x0c;  off[3] = y1c*W + x1c;
    wt[0] = (vx0 && vy0) ? (1.f-tx)*(1.f-ty) : 0.f;
    wt[1] = (vx1 && vy0) ? tx*(1.f-ty)       : 0.f;
    wt[2] = (vx0 && vy1) ? (1.f-tx)*ty       : 0.f;
    wt[3] = (vx1 && vy1) ? tx*ty             : 0.f;
}

__device__ __forceinline__ float4 gather4(const float4* __restrict__ b,
                                          const int* off, const float* wt) {
    float4 p0 = b[off[0]], p1 = b[off[1]], p2 = b[off[2]], p3 = b[off[3]];
    float4 a;
    a.x = wt[0]*p0.x + wt[1]*p1.x + wt[2]*p2.x + wt[3]*p3.x;
    a.y = wt[0]*p0.y + wt[1]*p1.y + wt[2]*p2.y + wt[3]*p3.y;
    a.z = wt[0]*p0.z + wt[1]*p1.z + wt[2]*p2.z + wt[3]*p3.z;
    a.w = wt[0]*p0.w + wt[1]*p1.w + wt[2]*p2.w + wt[3]*p3.w;
    return a;
}

__device__ __forceinline__ float4 var3(float4 r, float4 a1, float4 a2) {
    float4 o;
    float s, q, m;
    s = r.x + a1.x + a2.x; q = r.x*r.x + a1.x*a1.x + a2.x*a2.x;
    m = s*(1.f/3.f); o.x = q*(1.f/3.f) - m*m;
    s = r.y + a1.y + a2.y; q = r.y*r.y + a1.y*a1.y + a2.y*a2.y;
    m = s*(1.f/3.f); o.y = q*(1.f/3.f) - m*m;
    s = r.z + a1.z + a2.z; q = r.z*r.z + a1.z*a1.z + a2.z*a2.z;
    m = s*(1.f/3.f); o.z = q*(1.f/3.f) - m*m;
    s = r.w + a1.w + a2.w; q = r.w*r.w + a1.w*a1.w + a2.w*a2.w;
    m = s*(1.f/3.f); o.w = q*(1.f/3.f) - m*m;
    return o;
}

// ---------------- var kernel: single voxel per thread, max occupancy ----------------
template<int C, int D, int H, int W, bool STAGE2>
__global__ void __launch_bounds__(256)
var_kernel(int stage) {
    constexpr int HW = H * W;
    constexpr int CG = C / 4;
    constexpr int DHW = D * HW;

    int idx = blockIdx.x * blockDim.x + threadIdx.x;
    if (idx >= DHW) return;
    int hw = idx % HW;
    int d  = idx / HW;
    int h = hw / W, w = hw % W;

    float base, step;
    if (STAGE2) { base = g_bs[hw]; step = g_bs[HWS2 + hw]; }
    else        { base = g_dmin;   step = g_dstep; }
    float dep = fmaf(step, (float)d, base);

    int   off[2][4];
    float wt[2][4];
    float fx = (float)w, fy = (float)h;
    project_offsets<H, W>(g_rot[stage][0], g_trans[stage][0], fx, fy, dep, off[0], wt[0]);
    project_offsets<H, W>(g_rot[stage][1], g_trans[stage][1], fx, fy, dep, off[1], wt[1]);

    const float4* ft0 = g_ft + hw;
    const float4* ft1 = g_ft + (size_t)(1*CG) * HW;
    const float4* ft2 = g_ft + (size_t)(2*CG) * HW;

    #pragma unroll
    for (int cg = 0; cg < CG; cg++) {
        float4 r4 = ft0[(size_t)cg * HW];
        float4 v = var3(r4, gather4(ft1 + (size_t)cg * HW, off[0], wt[0]),
                            gather4(ft2 + (size_t)cg * HW, off[1], wt[1]));
        g_V[(size_t)cg*DHW + idx] = v;
    }
}

// ---------------- tap kernel: depth-folded dense reduction (f32x2) ----------------
// B[j][d][hw] = sum_{kd,c} var[c][d+kd-1][hw] * w[c][kd*9+j]
// Reads var rows d-1,d,d+1 (dense, L2-resident), writes 9 planes.
template<int C, int D, int H, int W>
__global__ void __launch_bounds__(256)
tap_kernel(const float* __restrict__ wconv) {   // (C, 27)
    constexpr int HW  = H * W;
    constexpr int CG  = C / 4;
    constexpr int DHW = D * HW;

    // swp[(kd*9+j)*CG + cg] = packed weight pairs for 4 channels at tap (kd,j)
    __shared__ ulonglong2 swp[27 * CG];
    for (int i = threadIdx.x; i < 27*CG; i += blockDim.x) {
        int k = i / CG, cg = i % CG;
        ulonglong2 e;
        e.x = pk2(wconv[(4*cg + 0)*27 + k], wconv[(4*cg + 1)*27 + k]);
        e.y = pk2(wconv[(4*cg + 2)*27 + k], wconv[(4*cg + 3)*27 + k]);
        swp[i] = e;
    }
    __syncthreads();

    int t = blockIdx.x * blockDim.x + threadIdx.x;
    if (t >= DHW) return;
    int d = t / HW;

    bool hasM = (d > 0);
    bool hasP = (d < D-1);

    unsigned long long acc[9];
    #pragma unroll
    for (int j = 0; j < 9; j++) acc[j] = 0ULL;

    #pragma unroll
    for (int cg = 0; cg < CG; cg++) {
        const float4* vp = &g_V[(size_t)cg*DHW + t];
        ulonglong2 vm, v0, vp1;
        v0 = *reinterpret_cast<const ulonglong2*>(vp);
        if (hasM) vm  = *reinterpret_cast<const ulonglong2*>(vp - HW);
        else      { vm.x = 0ULL; vm.y = 0ULL; }
        if (hasP) vp1 = *reinterpret_cast<const ulonglong2*>(vp + HW);
        else      { vp1.x = 0ULL; vp1.y = 0ULL; }

        #pragma unroll
        for (int j = 0; j < 9; j++) {
            // output d: kd=0 pairs var[d-1], kd=1 var[d], kd=2 var[d+1]
            ulonglong2 w0 = swp[(0*9 + j)*CG + cg];
            ulonglong2 w1 = swp[(1*9 + j)*CG + cg];
            ulonglong2 w2 = swp[(2*9 + j)*CG + cg];
            fma2(acc[j], vm.x,  w0.x);
            fma2(acc[j], vm.y,  w0.y);
            fma2(acc[j], v0.x,  w1.x);
            fma2(acc[j], v0.y,  w1.y);
            fma2(acc[j], vp1.x, w2.x);
            fma2(acc[j], vp1.y, w2.y);
        }
    }

    #pragma unroll
    for (int j = 0; j < 9; j++)
        g_B[(size_t)j*DHW + t] = upk2_sum(acc[j]);
}

// ---------------- cost: 9-tap 2D shifted-plane sum, 4 pixels per thread ----------------
template<int D, int H, int W>
__global__ void __launch_bounds__(256)
cost_kernel(const float* __restrict__ bias) {
    constexpr int HW = H * W;
    constexpr int W4 = W / 4;
    int t = blockIdx.x * blockDim.x + threadIdx.x;
    if (t >= D * H * W4) return;
    int wq = (t % W4) * 4;
    int r  = t / W4;
    int h = r % H;
    int d = r / H;

    float bb = bias[0];
    float4 s = make_float4(bb, bb, bb, bb);

    #pragma unroll
    for (int kh = 0; kh < 3; kh++) {
        int hh = h + kh - 1;
        if (hh < 0 || hh >= H) continue;
        #pragma unroll
        for (int kw = 0; kw < 3; kw++) {
            const float* row = g_B + (size_t)(kh*3 + kw)*(D*HW)
                                   + (size_t)d*HW + (size_t)hh*W;
            float4 v = *reinterpret_cast<const float4*>(row + wq);
            if (kw == 0) {          // shift -1
                float left = (wq > 0) ? row[wq-1] : 0.f;
                s.x += left; s.y += v.x; s.z += v.y; s.w += v.z;
            } else if (kw == 1) {   // shift 0
                s.x += v.x; s.y += v.y; s.z += v.z; s.w += v.w;
            } else {                // shift +1
                float right = (wq + 4 < W) ? row[wq+4] : 0.f;
                s.x += v.y; s.y += v.z; s.z += v.w; s.w += right;
            }
        }
    }
    *reinterpret_cast<float4*>(g_cost + (size_t)d*HW + (size_t)h*W + wq) = s;
}

// ---------------- per-pixel epilogue ----------------
template<int D, int H, int W, bool STAGE2>
__global__ void __launch_bounds__(256)
pixel_kernel(float* __restrict__ outd,
             float* __restrict__ outc,
             float* __restrict__ outv) {
    constexpr int HW = H * W;
    int p = blockIdx.x * blockDim.x + threadIdx.x;
    if (p >= HW) return;

    float e[D];
    float mx = -1e30f;
    #pragma unroll
    for (int d = 0; d < D; d++) { e[d] = g_cost[(size_t)d*HW + p]; mx = fmaxf(mx, e[d]); }
    float sum = 0.f;
    #pragma unroll
    for (int d = 0; d < D; d++) { e[d] = expf(e[d] - mx); sum += e[d]; }
    float inv = 1.0f / sum;
    float m1 = 0.f;
    #pragma unroll
    for (int d = 0; d < D; d++) {
        float pr = e[d] * inv;
        e[d] = pr;
        m1 += pr * (float)d;
    }

    float base, step;
    if (STAGE2) { base = g_bs[p]; step = g_bs[HWS2 + p]; }
    else        { base = g_dmin; step = g_dstep; }

    float depth = fmaf(step, m1, base);
    float var = 0.f;
    #pragma unroll
    for (int d = 0; d < D; d++) {
        float t = step * ((float)d - m1);
        var += e[d] * t * t;
    }
    int di = min(max((int)m1, 0), D-1);
    float conf = 0.f;
    #pragma unroll
    for (int d = 0; d < D; d++)
        if (d >= di-1 && d <= di+2) conf += e[d];

    outd[p] = depth;
    outc[p] = conf;
    outv[p] = 1.5f * sqrtf(fmaxf(var, 0.f));
}

// ---------------- launch ----------------
extern "C" void kernel_launch(void* const* d_in, const int* in_sizes, int n_in,
                              void* d_out, int out_size) {
    const float* feats1 = (const float*)d_in[0];
    const float* feats2 = (const float*)d_in[1];
    const float* proj1  = (const float*)d_in[2];
    const float* proj2  = (const float*)d_in[3];
    const float* depthv = (const float*)d_in[4];
    const float* w1     = (const float*)d_in[6];
    const float* b1     = (const float*)d_in[7];
    const float* w2     = (const float*)d_in[8];
    const float* b2     = (const float*)d_in[9];

    float* out = (float*)d_out;
    float* o_d1 = out;
    float* o_c1 = out + HWS1;
    float* o_v1 = out + 2*HWS1;
    float* o_d2 = out + 3*HWS1;
    float* o_c2 = out + 3*HWS1 + HWS2;
    float* o_v2 = out + 3*HWS1 + 2*HWS2;

    setup_kernel<<<1, 1>>>(proj1, proj2, depthv);                             // 1
    transpose_kernel<C1, HWS1><<<(3*(C1/4)*HWS1 + 255)/256, 256>>>(feats1);   // 2
    pad_kernel<<<1, 32>>>(0);                                                  // 3

    // ---- stage 1 (C=32, D=48, 128x160) ----
    {
        int nvox = ND1 * HWS1;   // 983040
        var_kernel<C1, ND1, H1, W1, false>                                     // 4 (profiled)
            <<<(nvox + 255)/256, 256>>>(0);
        tap_kernel<C1, ND1, H1, W1>
            <<<(nvox + 255)/256, 256>>>(w1);
        cost_kernel<ND1, H1, W1>
            <<<(ND1*H1*(W1/4) + 255)/256, 256>>>(b1);
        pixel_kernel<ND1, H1, W1, false>
            <<<(HWS1 + 255)/256, 256>>>(o_d1, o_c1, o_v1);
    }

    // ---- stage 2 (C=16, D=8, 256x320) ----
    {
        int nvox = ND2 * HWS2;   // 655360
        transpose_kernel<C2, HWS2><<<(3*(C2/4)*HWS2 + 255)/256, 256>>>(feats2);
        bs2_kernel<<<(HWS2 + 255)/256, 256>>>(o_d1, o_v1);
        var_kernel<C2, ND2, H2, W2, true>
            <<<(nvox + 255)/256, 256>>>(1);
        tap_kernel<C2, ND2, H2, W2>
            <<<(nvox + 255)/256, 256>>>(w2);
        cost_kernel<ND2, H2, W2>
            <<<(ND2*H2*(W2/4) + 255)/256, 256>>>(b2);
        pixel_kernel<ND2, H2, W2, true>
            <<<(HWS2 + 255)/256, 256>>>(o_d2, o_c2, o_v2);
    }
}